// round 9
// baseline (speedup 1.0000x reference)
#include <cuda_runtime.h>
#include <math.h>

// YOLOv1 loss — fully fused: one main kernel (4 samples/CTA, warp-per-sample
// pairing, single __syncthreads) + one tiny final-reduce kernel.
//
// Exactness: max_iou is only ever compared against 0, and union>0 always
// (w,h >= 0.05), so cmask == "exists masked pred box with intersection > 0".
// The intersection arithmetic (cx - 0.5f*w, min/max/sub, >0 test) matches the
// reference ops exactly, so the decision is bit-identical.
//
// No persistent state: g_part is fully overwritten every run (graph-replay
// safe); no atomics, no counters, no fences.

#define CELLS 49
#define CH 30
#define FPS (CELLS * CH)          // 1470 floats per sample
#define SPC 4                     // samples per CTA
#define TPB 128                   // 4 warps, one per sample
#define MAXB 8192

__device__ __align__(16) float4 g_part[MAXB];   // per-sample {noobj, cls, coord, objc}

// ---------------------------------------------------------------------------
// Main kernel: stage 4 samples with float4, then warp-autonomous per-sample.
// ---------------------------------------------------------------------------
__global__ __launch_bounds__(TPB) void yolo_fused_kernel(
    const float* __restrict__ pred, const float* __restrict__ target,
    int B, int total_floats)
{
    __shared__ float sp[SPC * FPS];
    __shared__ float st[SPC * FPS];
    __shared__ int s_list[SPC][CELLS];

    const int tid  = threadIdx.x;
    const int lane = tid & 31;
    const int w    = tid >> 5;                      // warp == sample-in-CTA
    const int f0   = blockIdx.x * (SPC * FPS);      // 23520*blk -> 16B aligned
    const int flen = min(SPC * FPS, total_floats - f0);

    // ---- staging: all LDG.128 (every CTA base is 16B aligned) ----
    {
        const int nv4 = flen >> 2;                  // 1470 float4 per tensor (full CTA)
        const float4* gp4 = (const float4*)(pred + f0);
        const float4* gt4 = (const float4*)(target + f0);
        float4* sp4 = (float4*)sp;
        float4* st4 = (float4*)st;
        #pragma unroll 4
        for (int i = tid; i < nv4; i += TPB) {
            sp4[i] = gp4[i];
            st4[i] = gt4[i];
        }
        for (int i = (nv4 << 2) + tid; i < flen; i += TPB) {  // partial-CTA tail
            sp[i] = pred[f0 + i];
            st[i] = target[f0 + i];
        }
    }
    __syncthreads();                                // the only CTA barrier

    const int s = blockIdx.x * SPC + w;             // global sample of this warp
    float accN = 0.f, accC = 0.f, coord = 0.f, objc = 0.f;

    if (s < B) {
        const float* ps = sp + w * FPS;
        const float* ts = st + w * FPS;

        // ---- phase 1: per-cell terms + ballot compaction of obj cells ----
        int nobj = 0;
        #pragma unroll
        for (int half = 0; half < 2; half++) {
            const int c = lane + 32 * half;
            bool isobj = false;
            if (c < CELLS) {
                const float* pc = ps + c * CH;
                const float* tc = ts + c * CH;
                if (tc[4] == 0.f) {                 // conf channel exactly 0/1
                    const float d4 = pc[4] - tc[4];
                    const float d9 = pc[9] - tc[9];
                    accN += d4 * d4 + d9 * d9;
                } else {
                    isobj = true;
                    float acc = 0.f;
                    #pragma unroll
                    for (int k = 10; k < CH; k++) {
                        const float d = pc[k] - tc[k];
                        acc += d * d;
                    }
                    accC += acc;
                }
            }
            const unsigned m = __ballot_sync(0xffffffffu, isobj);
            if (isobj)
                s_list[w][nobj + __popc(m & ((1u << lane) - 1u))] = c;
            nobj += __popc(m);
        }
        __syncwarp();

        // ---- phase 2: in-warp pairing (existence test with early exit) ----
        const int nbox = 2 * nobj;
        for (int i = lane; i < nbox; i += 32) {
            const int toff = s_list[w][i >> 1] * CH + 5 * (i & 1);
            const float* tb = ts + toff;
            const float tcx = tb[0], tcy = tb[1], tw = tb[2], th = tb[3];
            const float tx0 = tcx - 0.5f * tw, ty0 = tcy - 0.5f * th;
            const float tx1 = tcx + 0.5f * tw, ty1 = tcy + 0.5f * th;

            bool found = false;
            for (int j = 0; j < nbox; j++) {        // j warp-uniform -> LDS broadcast
                const int po = s_list[w][j >> 1] * CH + 5 * (j & 1);
                const float pcx = ps[po],     pcy = ps[po + 1];
                const float pw  = ps[po + 2], ph  = ps[po + 3];
                const float ix = fminf(pcx + 0.5f * pw, tx1) - fmaxf(pcx - 0.5f * pw, tx0);
                const float iy = fminf(pcy + 0.5f * ph, ty1) - fmaxf(pcy - 0.5f * ph, ty0);
                if (ix > 0.f && iy > 0.f && ix * iy > 0.f) { found = true; break; }
            }
            if (found) {
                const float* pb = ps + toff;
                const float dx = pb[0] - tcx;
                const float dy = pb[1] - tcy;
                const float dw = sqrtf(pb[2]) - sqrtf(tw);
                const float dh = sqrtf(pb[3]) - sqrtf(th);
                coord += dx * dx + dy * dy + dw * dw + dh * dh;
                const float dc = pb[4] - tb[4];
                objc += dc * dc;
            }
        }
    }

    // ---- in-warp reduction of 4 scalars, one float4 store per sample ----
    #pragma unroll
    for (int o = 16; o > 0; o >>= 1) {
        accN  += __shfl_down_sync(0xffffffffu, accN, o);
        accC  += __shfl_down_sync(0xffffffffu, accC, o);
        coord += __shfl_down_sync(0xffffffffu, coord, o);
        objc  += __shfl_down_sync(0xffffffffu, objc, o);
    }
    if (lane == 0 && s < B)
        g_part[s] = make_float4(accN, accC, coord, objc);
}

// ---------------------------------------------------------------------------
// Final kernel: 1 CTA x 1024 threads, fixed-order double reduction.
// ---------------------------------------------------------------------------
__global__ __launch_bounds__(1024) void yolo_final_kernel(float* __restrict__ out, int B)
{
    const int tid  = threadIdx.x;
    const int lane = tid & 31, warp = tid >> 5;

    double a0 = 0.0, a1 = 0.0, a2 = 0.0, a3 = 0.0;   // noobj, cls, coord, objc
    for (int i = tid; i < B; i += 1024) {
        const float4 v = g_part[i];
        a0 += (double)v.x;
        a1 += (double)v.y;
        a2 += (double)v.z;
        a3 += (double)v.w;
    }
    #pragma unroll
    for (int o = 16; o > 0; o >>= 1) {
        a0 += __shfl_down_sync(0xffffffffu, a0, o);
        a1 += __shfl_down_sync(0xffffffffu, a1, o);
        a2 += __shfl_down_sync(0xffffffffu, a2, o);
        a3 += __shfl_down_sync(0xffffffffu, a3, o);
    }
    __shared__ double sd[4][32];
    if (lane == 0) { sd[0][warp] = a0; sd[1][warp] = a1; sd[2][warp] = a2; sd[3][warp] = a3; }
    __syncthreads();
    if (tid == 0) {
        double r0 = 0, r1 = 0, r2 = 0, r3 = 0;
        #pragma unroll
        for (int k = 0; k < 32; k++) {
            r0 += sd[0][k]; r1 += sd[1][k]; r2 += sd[2][k]; r3 += sd[3][k];
        }
        const double inv = 1.0 / (double)B;
        const double cls_l = r1 * inv;
        const double obj_l = (r3 + 0.5 * r0) * inv;
        const double crd_l = r2 * 5.0 * inv;
        out[0] = (float)(cls_l + obj_l + crd_l);
        out[1] = (float)cls_l;
        out[2] = (float)obj_l;
        out[3] = (float)crd_l;
    }
}

extern "C" void kernel_launch(void* const* d_in, const int* in_sizes, int n_in,
                              void* d_out, int out_size)
{
    const float* pred = (const float*)d_in[0];
    const float* target = (const float*)d_in[1];
    const int B = in_sizes[0] / FPS;
    const int total_floats = B * FPS;
    const int ncta = (B + SPC - 1) / SPC;

    yolo_fused_kernel<<<ncta, TPB>>>(pred, target, B, total_floats);
    yolo_final_kernel<<<1, 1024>>>((float*)d_out, B);
}

// round 10
// speedup vs baseline: 1.5434x; 1.5434x over previous
#include <cuda_runtime.h>
#include <math.h>

// YOLOv1 loss — single launch. Main body identical to R9 (4 samples/CTA,
// warp-per-sample pairing; measured ~24.7us). The separate final-reduce
// kernel (measured 33.4us for trivial work: single CTA, FP64, no latency
// hiding) is replaced by a last-CTA reduction inside the same launch.
//
// Exactness: max_iou is only ever compared against 0, and union>0 always
// (w,h >= 0.05), so cmask == "exists masked pred box with intersection > 0".
// The intersection arithmetic (cx - 0.5f*w, min/max/sub, >0 test) matches the
// reference ops exactly, so the decision is bit-identical.
//
// Graph-replay invariants: g_partCTA fully overwritten each run; g_count is 0
// at the start of every launch (reset by the last CTA after use).

#define CELLS 49
#define CH 30
#define FPS (CELLS * CH)          // 1470 floats per sample
#define SPC 4                     // samples per CTA
#define TPB 128                   // 4 warps, one per sample
#define MAXB 8192
#define MAXCTA ((MAXB + SPC - 1) / SPC)

__device__ __align__(16) float4 g_partCTA[MAXCTA];  // per-CTA {noobj, cls, coord, objc}
__device__ unsigned int g_count = 0;

__global__ __launch_bounds__(TPB) void yolo_fused_kernel(
    const float* __restrict__ pred, const float* __restrict__ target,
    float* __restrict__ out, int B, int total_floats, int ncta)
{
    __shared__ float sp[SPC * FPS];
    __shared__ float st[SPC * FPS];
    __shared__ int s_list[SPC][CELLS];
    __shared__ float4 s_red[4];
    __shared__ int s_last;

    const int tid  = threadIdx.x;
    const int lane = tid & 31;
    const int w    = tid >> 5;                      // warp == sample-in-CTA
    const int f0   = blockIdx.x * (SPC * FPS);      // 23520*blk -> 16B aligned
    const int flen = min(SPC * FPS, total_floats - f0);

    // ---- staging: all LDG.128 (every CTA base is 16B aligned) ----
    {
        const int nv4 = flen >> 2;
        const float4* gp4 = (const float4*)(pred + f0);
        const float4* gt4 = (const float4*)(target + f0);
        float4* sp4 = (float4*)sp;
        float4* st4 = (float4*)st;
        #pragma unroll 4
        for (int i = tid; i < nv4; i += TPB) {
            sp4[i] = gp4[i];
            st4[i] = gt4[i];
        }
        for (int i = (nv4 << 2) + tid; i < flen; i += TPB) {
            sp[i] = pred[f0 + i];
            st[i] = target[f0 + i];
        }
    }
    __syncthreads();

    const int s = blockIdx.x * SPC + w;             // global sample of this warp
    float accN = 0.f, accC = 0.f, coord = 0.f, objc = 0.f;

    if (s < B) {
        const float* ps = sp + w * FPS;
        const float* ts = st + w * FPS;

        // ---- phase 1: per-cell terms + ballot compaction of obj cells ----
        int nobj = 0;
        #pragma unroll
        for (int half = 0; half < 2; half++) {
            const int c = lane + 32 * half;
            bool isobj = false;
            if (c < CELLS) {
                const float* pc = ps + c * CH;
                const float* tc = ts + c * CH;
                if (tc[4] == 0.f) {                 // conf channel exactly 0/1
                    const float d4 = pc[4] - tc[4];
                    const float d9 = pc[9] - tc[9];
                    accN += d4 * d4 + d9 * d9;
                } else {
                    isobj = true;
                    float acc = 0.f;
                    #pragma unroll
                    for (int k = 10; k < CH; k++) {
                        const float d = pc[k] - tc[k];
                        acc += d * d;
                    }
                    accC += acc;
                }
            }
            const unsigned m = __ballot_sync(0xffffffffu, isobj);
            if (isobj)
                s_list[w][nobj + __popc(m & ((1u << lane) - 1u))] = c;
            nobj += __popc(m);
        }
        __syncwarp();

        // ---- phase 2: in-warp pairing (existence test with early exit) ----
        const int nbox = 2 * nobj;
        for (int i = lane; i < nbox; i += 32) {
            const int toff = s_list[w][i >> 1] * CH + 5 * (i & 1);
            const float* tb = ts + toff;
            const float tcx = tb[0], tcy = tb[1], tw = tb[2], th = tb[3];
            const float tx0 = tcx - 0.5f * tw, ty0 = tcy - 0.5f * th;
            const float tx1 = tcx + 0.5f * tw, ty1 = tcy + 0.5f * th;

            bool found = false;
            for (int j = 0; j < nbox; j++) {        // j warp-uniform -> LDS broadcast
                const int po = s_list[w][j >> 1] * CH + 5 * (j & 1);
                const float pcx = ps[po],     pcy = ps[po + 1];
                const float pw  = ps[po + 2], ph  = ps[po + 3];
                const float ix = fminf(pcx + 0.5f * pw, tx1) - fmaxf(pcx - 0.5f * pw, tx0);
                const float iy = fminf(pcy + 0.5f * ph, ty1) - fmaxf(pcy - 0.5f * ph, ty0);
                if (ix > 0.f && iy > 0.f && ix * iy > 0.f) { found = true; break; }
            }
            if (found) {
                const float* pb = ps + toff;
                const float dx = pb[0] - tcx;
                const float dy = pb[1] - tcy;
                const float dw = sqrtf(pb[2]) - sqrtf(tw);
                const float dh = sqrtf(pb[3]) - sqrtf(th);
                coord += dx * dx + dy * dy + dw * dw + dh * dh;
                const float dc = pb[4] - tb[4];
                objc += dc * dc;
            }
        }
    }

    // ---- warp reduce, then CTA combine to one float4 ----
    #pragma unroll
    for (int o = 16; o > 0; o >>= 1) {
        accN  += __shfl_down_sync(0xffffffffu, accN, o);
        accC  += __shfl_down_sync(0xffffffffu, accC, o);
        coord += __shfl_down_sync(0xffffffffu, coord, o);
        objc  += __shfl_down_sync(0xffffffffu, objc, o);
    }
    if (lane == 0)
        s_red[w] = make_float4(accN, accC, coord, objc);
    __syncthreads();

    if (tid == 0) {
        float4 r = s_red[0];
        #pragma unroll
        for (int k = 1; k < 4; k++) {
            r.x += s_red[k].x; r.y += s_red[k].y;
            r.z += s_red[k].z; r.w += s_red[k].w;
        }
        g_partCTA[blockIdx.x] = r;
        __threadfence();
        const unsigned int old = atomicAdd(&g_count, 1u);
        s_last = (old == (unsigned int)(ncta - 1)) ? 1 : 0;
    }
    __syncthreads();

    if (!s_last) return;

    // ---- last CTA: final reduction over ncta float4 (L2-hot, fixed order) ----
    double a0 = 0.0, a1 = 0.0, a2 = 0.0, a3 = 0.0;
    for (int i = tid; i < ncta; i += TPB) {
        const float4 v = g_partCTA[i];
        a0 += (double)v.x;
        a1 += (double)v.y;
        a2 += (double)v.z;
        a3 += (double)v.w;
    }
    #pragma unroll
    for (int o = 16; o > 0; o >>= 1) {
        a0 += __shfl_down_sync(0xffffffffu, a0, o);
        a1 += __shfl_down_sync(0xffffffffu, a1, o);
        a2 += __shfl_down_sync(0xffffffffu, a2, o);
        a3 += __shfl_down_sync(0xffffffffu, a3, o);
    }
    __shared__ double sd[4][4];
    if (lane == 0) { sd[0][w] = a0; sd[1][w] = a1; sd[2][w] = a2; sd[3][w] = a3; }
    __syncthreads();
    if (tid == 0) {
        double r0 = 0, r1 = 0, r2 = 0, r3 = 0;
        #pragma unroll
        for (int k = 0; k < 4; k++) {
            r0 += sd[0][k]; r1 += sd[1][k]; r2 += sd[2][k]; r3 += sd[3][k];
        }
        const double inv = 1.0 / (double)B;
        const double cls_l = r1 * inv;
        const double obj_l = (r3 + 0.5 * r0) * inv;
        const double crd_l = r2 * 5.0 * inv;
        out[0] = (float)(cls_l + obj_l + crd_l);
        out[1] = (float)cls_l;
        out[2] = (float)obj_l;
        out[3] = (float)crd_l;
        g_count = 0u;                               // restore replay invariant
    }
}

extern "C" void kernel_launch(void* const* d_in, const int* in_sizes, int n_in,
                              void* d_out, int out_size)
{
    const float* pred = (const float*)d_in[0];
    const float* target = (const float*)d_in[1];
    const int B = in_sizes[0] / FPS;
    const int total_floats = B * FPS;
    const int ncta = (B + SPC - 1) / SPC;

    yolo_fused_kernel<<<ncta, TPB>>>(pred, target, (float*)d_out, B, total_floats, ncta);
}

// round 11
// speedup vs baseline: 1.8596x; 1.2049x over previous
#include <cuda_runtime.h>
#include <math.h>

// YOLOv1 loss — single launch, R10 structure with cp.async (LDGSTS) staging.
// R10's LDG->STS staging was register-limited to ~4 in-flight loads/warp
// (2.3TB/s at 22.8% occupancy). cp.async removes registers from the load
// path: ~23 16B async copies per thread, ~188KB in flight per SM.
//
// Exactness: max_iou is only ever compared against 0, and union>0 always
// (w,h >= 0.05), so cmask == "exists masked pred box with intersection > 0".
// The intersection arithmetic (cx - 0.5f*w, min/max/sub, >0 test) matches the
// reference ops exactly, so the decision is bit-identical.
//
// Graph-replay invariants: g_partCTA fully overwritten each run; g_count is 0
// at the start of every launch (reset by the last CTA after use).

#define CELLS 49
#define CH 30
#define FPS (CELLS * CH)          // 1470 floats per sample
#define SPC 4                     // samples per CTA
#define TPB 128                   // 4 warps, one per sample
#define MAXB 8192
#define MAXCTA ((MAXB + SPC - 1) / SPC)

__device__ __align__(16) float4 g_partCTA[MAXCTA];  // per-CTA {noobj, cls, coord, objc}
__device__ unsigned int g_count = 0;

__global__ __launch_bounds__(TPB) void yolo_fused_kernel(
    const float* __restrict__ pred, const float* __restrict__ target,
    float* __restrict__ out, int B, int total_floats, int ncta)
{
    __shared__ __align__(16) float sp[SPC * FPS];
    __shared__ __align__(16) float st[SPC * FPS];
    __shared__ int s_list[SPC][CELLS];
    __shared__ float4 s_red[4];
    __shared__ int s_last;

    const int tid  = threadIdx.x;
    const int lane = tid & 31;
    const int w    = tid >> 5;                      // warp == sample-in-CTA
    const int f0   = blockIdx.x * (SPC * FPS);      // 23520*blk -> 16B aligned
    const int flen = min(SPC * FPS, total_floats - f0);

    // ---- staging via cp.async: no register residency, maximal MLP ----
    if (flen == SPC * FPS) {
        const int nv4 = (SPC * FPS) >> 2;           // 1470 float4 per tensor
        const float4* gp4 = (const float4*)(pred + f0);
        const float4* gt4 = (const float4*)(target + f0);
        const unsigned sp_b = (unsigned)__cvta_generic_to_shared(sp);
        const unsigned st_b = (unsigned)__cvta_generic_to_shared(st);
        for (int i = tid; i < nv4; i += TPB) {
            asm volatile("cp.async.cg.shared.global [%0], [%1], 16;\n"
                         :: "r"(sp_b + 16u * i), "l"(gp4 + i));
            asm volatile("cp.async.cg.shared.global [%0], [%1], 16;\n"
                         :: "r"(st_b + 16u * i), "l"(gt4 + i));
        }
        asm volatile("cp.async.commit_group;\n");
        asm volatile("cp.async.wait_group 0;\n" ::: "memory");
    } else {                                        // partial tail CTA (rare)
        for (int i = tid; i < flen; i += TPB) {
            sp[i] = pred[f0 + i];
            st[i] = target[f0 + i];
        }
    }
    __syncthreads();

    const int s = blockIdx.x * SPC + w;             // global sample of this warp
    float accN = 0.f, accC = 0.f, coord = 0.f, objc = 0.f;

    if (s < B) {
        const float* ps = sp + w * FPS;
        const float* ts = st + w * FPS;

        // ---- phase 1: per-cell terms + ballot compaction of obj cells ----
        int nobj = 0;
        #pragma unroll
        for (int half = 0; half < 2; half++) {
            const int c = lane + 32 * half;
            bool isobj = false;
            if (c < CELLS) {
                const float* pc = ps + c * CH;
                const float* tc = ts + c * CH;
                if (tc[4] == 0.f) {                 // conf channel exactly 0/1
                    const float d4 = pc[4] - tc[4];
                    const float d9 = pc[9] - tc[9];
                    accN += d4 * d4 + d9 * d9;
                } else {
                    isobj = true;
                    float acc = 0.f;
                    #pragma unroll
                    for (int k = 10; k < CH; k++) {
                        const float d = pc[k] - tc[k];
                        acc += d * d;
                    }
                    accC += acc;
                }
            }
            const unsigned m = __ballot_sync(0xffffffffu, isobj);
            if (isobj)
                s_list[w][nobj + __popc(m & ((1u << lane) - 1u))] = c;
            nobj += __popc(m);
        }
        __syncwarp();

        // ---- phase 2: in-warp pairing (existence test with early exit) ----
        const int nbox = 2 * nobj;
        for (int i = lane; i < nbox; i += 32) {
            const int toff = s_list[w][i >> 1] * CH + 5 * (i & 1);
            const float* tb = ts + toff;
            const float tcx = tb[0], tcy = tb[1], tw = tb[2], th = tb[3];
            const float tx0 = tcx - 0.5f * tw, ty0 = tcy - 0.5f * th;
            const float tx1 = tcx + 0.5f * tw, ty1 = tcy + 0.5f * th;

            bool found = false;
            for (int j = 0; j < nbox; j++) {        // j warp-uniform -> LDS broadcast
                const int po = s_list[w][j >> 1] * CH + 5 * (j & 1);
                const float pcx = ps[po],     pcy = ps[po + 1];
                const float pw  = ps[po + 2], ph  = ps[po + 3];
                const float ix = fminf(pcx + 0.5f * pw, tx1) - fmaxf(pcx - 0.5f * pw, tx0);
                const float iy = fminf(pcy + 0.5f * ph, ty1) - fmaxf(pcy - 0.5f * ph, ty0);
                if (ix > 0.f && iy > 0.f && ix * iy > 0.f) { found = true; break; }
            }
            if (found) {
                const float* pb = ps + toff;
                const float dx = pb[0] - tcx;
                const float dy = pb[1] - tcy;
                const float dw = sqrtf(pb[2]) - sqrtf(tw);
                const float dh = sqrtf(pb[3]) - sqrtf(th);
                coord += dx * dx + dy * dy + dw * dw + dh * dh;
                const float dc = pb[4] - tb[4];
                objc += dc * dc;
            }
        }
    }

    // ---- warp reduce, then CTA combine to one float4 ----
    #pragma unroll
    for (int o = 16; o > 0; o >>= 1) {
        accN  += __shfl_down_sync(0xffffffffu, accN, o);
        accC  += __shfl_down_sync(0xffffffffu, accC, o);
        coord += __shfl_down_sync(0xffffffffu, coord, o);
        objc  += __shfl_down_sync(0xffffffffu, objc, o);
    }
    if (lane == 0)
        s_red[w] = make_float4(accN, accC, coord, objc);
    __syncthreads();

    if (tid == 0) {
        float4 r = s_red[0];
        #pragma unroll
        for (int k = 1; k < 4; k++) {
            r.x += s_red[k].x; r.y += s_red[k].y;
            r.z += s_red[k].z; r.w += s_red[k].w;
        }
        g_partCTA[blockIdx.x] = r;
        __threadfence();
        const unsigned int old = atomicAdd(&g_count, 1u);
        s_last = (old == (unsigned int)(ncta - 1)) ? 1 : 0;
    }
    __syncthreads();

    if (!s_last) return;

    // ---- last CTA: final reduction over ncta float4 (L2-hot, fixed order) ----
    double a0 = 0.0, a1 = 0.0, a2 = 0.0, a3 = 0.0;
    for (int i = tid; i < ncta; i += TPB) {
        const float4 v = g_partCTA[i];
        a0 += (double)v.x;
        a1 += (double)v.y;
        a2 += (double)v.z;
        a3 += (double)v.w;
    }
    #pragma unroll
    for (int o = 16; o > 0; o >>= 1) {
        a0 += __shfl_down_sync(0xffffffffu, a0, o);
        a1 += __shfl_down_sync(0xffffffffu, a1, o);
        a2 += __shfl_down_sync(0xffffffffu, a2, o);
        a3 += __shfl_down_sync(0xffffffffu, a3, o);
    }
    __shared__ double sd[4][4];
    if (lane == 0) { sd[0][w] = a0; sd[1][w] = a1; sd[2][w] = a2; sd[3][w] = a3; }
    __syncthreads();
    if (tid == 0) {
        double r0 = 0, r1 = 0, r2 = 0, r3 = 0;
        #pragma unroll
        for (int k = 0; k < 4; k++) {
            r0 += sd[0][k]; r1 += sd[1][k]; r2 += sd[2][k]; r3 += sd[3][k];
        }
        const double inv = 1.0 / (double)B;
        const double cls_l = r1 * inv;
        const double obj_l = (r3 + 0.5 * r0) * inv;
        const double crd_l = r2 * 5.0 * inv;
        out[0] = (float)(cls_l + obj_l + crd_l);
        out[1] = (float)cls_l;
        out[2] = (float)obj_l;
        out[3] = (float)crd_l;
        g_count = 0u;                               // restore replay invariant
    }
}

extern "C" void kernel_launch(void* const* d_in, const int* in_sizes, int n_in,
                              void* d_out, int out_size)
{
    const float* pred = (const float*)d_in[0];
    const float* target = (const float*)d_in[1];
    const int B = in_sizes[0] / FPS;
    const int total_floats = B * FPS;
    const int ncta = (B + SPC - 1) / SPC;

    yolo_fused_kernel<<<ncta, TPB>>>(pred, target, (float*)d_out, B, total_floats, ncta);
}